// round 15
// baseline (speedup 1.0000x reference)
#include <cuda_runtime.h>
#include <cuda_bf16.h>
#include <math.h>
#include <stdint.h>

// Problem constants
constexpr int Bn = 4096;
constexpr int An = 32;
constexpr int Hn = 128;
constexpr int G4 = 4 * Hn;          // 512
constexpr int M_BIG = Bn * An;      // 131072
constexpr int BAH = Bn * An * Hn;   // 16,777,216

// -------------------- scratch --------------------
__device__ float g_hh[An * G4];                // interleaved (4h+gate) hidden bias
__device__ float g_logp[(size_t)An * Bn * 16]; // logit partials (8 MB)
__device__ unsigned long long g_argmax[An];
// pre-split weights (hi/lo bf16, chunk-linear 16B units)
__device__ __nv_bfloat16 g_wih_h[An * G4 * Hn];   // 4 MB, permuted gate layout
__device__ __nv_bfloat16 g_wih_l[An * G4 * Hn];
__device__ __nv_bfloat16 g_we_h[Hn * Hn], g_we_l[Hn * Hn];
__device__ __nv_bfloat16 g_wt_h[Hn * Hn], g_wt_l[Hn * Hn];

// ==================== helpers ====================
__device__ __forceinline__ uint32_t smem_u32(const void* p) {
    uint32_t a;
    asm("{ .reg .u64 t; cvta.to.shared.u64 t, %1; cvt.u32.u64 %0, t; }"
        : "=r"(a) : "l"(p));
    return a;
}
__device__ __forceinline__ uint32_t pk(float k0, float k1) {
    uint32_t r;
    asm("cvt.rn.satfinite.bf16x2.f32 %0, %1, %2;" : "=r"(r) : "f"(k1), "f"(k0));
    return r;
}
__device__ __forceinline__ void ldsm_x4(uint32_t* r, uint32_t addr) {
    asm volatile("ldmatrix.sync.aligned.m8n8.x4.shared.b16 {%0,%1,%2,%3}, [%4];"
                 : "=r"(r[0]), "=r"(r[1]), "=r"(r[2]), "=r"(r[3]) : "r"(addr));
}
__device__ __forceinline__ void mma_bf16(float* d, const uint32_t* a, const uint32_t* b) {
    asm volatile(
        "mma.sync.aligned.m16n8k16.row.col.f32.bf16.bf16.f32 "
        "{%0,%1,%2,%3}, {%4,%5,%6,%7}, {%8,%9}, {%0,%1,%2,%3};"
        : "+f"(d[0]), "+f"(d[1]), "+f"(d[2]), "+f"(d[3])
        : "r"(a[0]), "r"(a[1]), "r"(a[2]), "r"(a[3]), "r"(b[0]), "r"(b[1]));
}
// fast transcendentals (MUFU-based); error ~1e-6 << bf16-split noise ~1e-4
__device__ __forceinline__ float fsig(float x) {
    return __fdividef(1.0f, 1.0f + __expf(-x));
}
__device__ __forceinline__ float ftanh(float x) {
    float t = __expf(-2.0f * x);
    return __fdividef(1.0f - t, 1.0f + t);
}

// -------------------- SMEM layouts --------------------
// k_out (unchanged, 128-row tile): chunk tiles 128x64 bf16 (16 KB each)
constexpr int OF_AH = 0;
constexpr int OF_AL = 16384;
constexpr int OF_BH = 32768;
constexpr int OF_BL = 49152;           // tiles end 65536
constexpr int OF_MISC = 69632;         // stage (128x132 f32) aliases tiles
constexpr int SMEM_G = 72192;

// k_lstm 64-row tile: A full-K 16 KB x2, B chunk 16 KB x2; stage aliases B-hi
constexpr int L_AH = 0;
constexpr int L_AL = 16384;
constexpr int L_BH = 32768;
constexpr int L_BL = 49152;            // tiles end 65536
constexpr int L_MISC = 65536;          // s_bias 512 + s_c0 128 + s_wg 256 floats
constexpr int SMEM_L = 69632;          // 3 CTAs/SM (3x69632 = 208896 <= 228KB)

__device__ __forceinline__ uint32_t su(int row, int u) {
    return (uint32_t)(row * 128 + ((u ^ (row & 7)) << 4));
}
__device__ __forceinline__ uint32_t suA(int row, int u) {
    return (uint32_t)(row * 256 + (((u & 7) ^ (row & 7)) << 4) + ((u >> 3) << 7));
}
__device__ __forceinline__ int sidx(int r, int c) {
    return r * 64 + (c ^ ((r & 7) << 3));
}

// split 8 floats -> hi/lo bf16x2 quads at given swizzled byte offset
__device__ __forceinline__ void split8(char* sm, int hib, int lob, uint32_t off,
                                       const float* v) {
    float h[8];
    #pragma unroll
    for (int j = 0; j < 8; j++) h[j] = __bfloat162float(__float2bfloat16(v[j]));
    uint4 hi = make_uint4(pk(v[0], v[1]), pk(v[2], v[3]), pk(v[4], v[5]), pk(v[6], v[7]));
    uint4 lo = make_uint4(pk(v[0] - h[0], v[1] - h[1]), pk(v[2] - h[2], v[3] - h[3]),
                          pk(v[4] - h[4], v[5] - h[5]), pk(v[6] - h[6], v[7] - h[7]));
    *reinterpret_cast<uint4*>(sm + hib + off) = hi;
    *reinterpret_cast<uint4*>(sm + lob + off) = lo;
}

// split 8 floats into two global uint4 slots (for weight prep)
__device__ __forceinline__ void split8_g(__nv_bfloat16* gh, __nv_bfloat16* gl,
                                         const float* v) {
    float h[8];
    #pragma unroll
    for (int j = 0; j < 8; j++) h[j] = __bfloat162float(__float2bfloat16(v[j]));
    uint4 hi = make_uint4(pk(v[0], v[1]), pk(v[2], v[3]), pk(v[4], v[5]), pk(v[6], v[7]));
    uint4 lo = make_uint4(pk(v[0] - h[0], v[1] - h[1]), pk(v[2] - h[2], v[3] - h[3]),
                          pk(v[4] - h[4], v[5] - h[5]), pk(v[6] - h[6], v[7] - h[7]));
    *reinterpret_cast<uint4*>(gh) = hi;
    *reinterpret_cast<uint4*>(gl) = lo;
}

// copy a pre-split 128x64 chunk (1024 16B units x2) into swizzled tiles
__device__ __forceinline__ void copy_tile(char* sm, int hib, int lob,
                                          const __nv_bfloat16* __restrict__ wh,
                                          const __nv_bfloat16* __restrict__ wl,
                                          int tid) {
    #pragma unroll
    for (int i = 0; i < 4; i++) {
        int idx = tid + i * 256;
        int row = idx >> 3, u = idx & 7;
        uint32_t off = su(row, u);
        *reinterpret_cast<uint4*>(sm + hib + off) =
            *reinterpret_cast<const uint4*>(wh + idx * 8);
        *reinterpret_cast<uint4*>(sm + lob + off) =
            *reinterpret_cast<const uint4*>(wl + idx * 8);
    }
}

// load+split a ROWSx64 fp32 chunk into hi/lo chunk tiles
template <int ROWS>
__device__ __forceinline__ void load_tile(char* sm, int hib, int lob,
                                          const float* __restrict__ src, int lda,
                                          int k0, int tid) {
    #pragma unroll
    for (int i = 0; i < ROWS * 8 / 256; i++) {
        int idx = tid + i * 256;
        int row = idx >> 3, u = idx & 7;
        const float* p = src + (size_t)row * lda + k0 + u * 8;
        float v[8];
        float4 v0 = *reinterpret_cast<const float4*>(p);
        float4 v1 = *reinterpret_cast<const float4*>(p + 4);
        v[0] = v0.x; v[1] = v0.y; v[2] = v0.z; v[3] = v0.w;
        v[4] = v1.x; v[5] = v1.y; v[6] = v1.z; v[7] = v1.w;
        split8(sm, hib, lob, su(row, u), v);
    }
}

// 3-pass split MMA over one 64-K chunk; A (hi+lo) register-resident per ks.
// MT = number of 16-row A tiles per warp. Pass order per acc: hh, lh, hl.
template <bool AFULL, int MT>
__device__ __forceinline__ void mma_chunk(uint32_t sb, int aHi, int aLo, int bHi,
                                          int bLo, int kcA, int wm, int wn, int lane,
                                          float acc[MT][8][4]) {
    const int arow = (lane & 7) + ((lane >> 3) & 1) * 8;
    const int akq  = lane >> 4;
    const int bnt  = (lane >> 4) & 1;
    const int bkq  = (lane >> 3) & 1;
    const int brow = lane & 7;
    #pragma unroll
    for (int ks = 0; ks < 4; ks++) {
        uint32_t aH[MT][4], aL[MT][4], b[4][2];
        const int uA = (AFULL ? kcA * 8 : 0) + ks * 2 + akq;
        const int uB = ks * 2 + bkq;
        #pragma unroll
        for (int mt = 0; mt < MT; mt++) {
            int r = wm + mt * 16 + arow;
            uint32_t offA = AFULL ? suA(r, uA) : su(r, uA);
            ldsm_x4(aH[mt], sb + aHi + offA);
            ldsm_x4(aL[mt], sb + aLo + offA);
        }
        #pragma unroll
        for (int hf = 0; hf < 2; hf++) {
            #pragma unroll
            for (int nt2 = 0; nt2 < 4; nt2 += 2)
                ldsm_x4(&b[nt2][0],
                        sb + bHi + su(wn + (hf * 4 + nt2 + bnt) * 8 + brow, uB));
            #pragma unroll
            for (int mt = 0; mt < MT; mt++)
                #pragma unroll
                for (int nt = 0; nt < 4; nt++)
                    mma_bf16(acc[mt][hf * 4 + nt], aH[mt], b[nt]);
            #pragma unroll
            for (int mt = 0; mt < MT; mt++)
                #pragma unroll
                for (int nt = 0; nt < 4; nt++)
                    mma_bf16(acc[mt][hf * 4 + nt], aL[mt], b[nt]);
            #pragma unroll
            for (int nt2 = 0; nt2 < 4; nt2 += 2)
                ldsm_x4(&b[nt2][0],
                        sb + bLo + su(wn + (hf * 4 + nt2 + bnt) * 8 + brow, uB));
            #pragma unroll
            for (int mt = 0; mt < MT; mt++)
                #pragma unroll
                for (int nt = 0; nt < 4; nt++)
                    mma_bf16(acc[mt][hf * 4 + nt], aH[mt], b[nt]);
        }
    }
}

__device__ __forceinline__ void stage_acc(float* stage, int wm, int wn, int lane,
                                          float acc[2][8][4]) {
    const int grp = lane >> 2, qp = lane & 3;
    #pragma unroll
    for (int mt = 0; mt < 2; mt++)
        #pragma unroll
        for (int nt = 0; nt < 8; nt++) {
            int r = wm + mt * 16 + grp;
            int c = wn + nt * 8 + qp * 2;
            stage[r * 132 + c] = acc[mt][nt][0];
            stage[r * 132 + c + 1] = acc[mt][nt][1];
            stage[(r + 8) * 132 + c] = acc[mt][nt][2];
            stage[(r + 8) * 132 + c + 1] = acc[mt][nt][3];
        }
}

// stage one 64-col half into the sidx layout (warps owning that half write)
template <int MT>
__device__ __forceinline__ void stage_half(float* stage, int wm, int wn, int ph,
                                           int lane, float acc[MT][8][4]) {
    if (wn == ph * 64) {
        const int grp = lane >> 2, qp = lane & 3;
        #pragma unroll
        for (int mt = 0; mt < MT; mt++)
            #pragma unroll
            for (int nt = 0; nt < 8; nt++) {
                int r = wm + mt * 16 + grp;
                int c = nt * 8 + qp * 2;
                *reinterpret_cast<float2*>(&stage[sidx(r, c)]) =
                    make_float2(acc[mt][nt][0], acc[mt][nt][1]);
                *reinterpret_cast<float2*>(&stage[sidx(r + 8, c)]) =
                    make_float2(acc[mt][nt][2], acc[mt][nt][3]);
            }
    }
}

#define ZERO_ACC_N(acc, MT)                                               \
    _Pragma("unroll") for (int mt = 0; mt < MT; mt++)                     \
        _Pragma("unroll") for (int nt = 0; nt < 8; nt++)                  \
            _Pragma("unroll") for (int e = 0; e < 4; e++) acc[mt][nt][e] = 0.f;

// ==================== prep: split weights ====================
__global__ void k_prep_wih(const float* __restrict__ Wih) {
    int g = blockIdx.x * blockDim.x + threadIdx.x;    // 262144 units
    int z = g >> 13, r = g & 8191;
    int nc = r >> 11, r2 = r & 2047;
    int kc = r2 >> 10, t = r2 & 1023;
    int row = t >> 3, u = t & 7;
    int ng = nc * 128 + row;
    int srow = (ng & 3) * 128 + (ng >> 2);
    const float* p = Wih + ((size_t)z * G4 + srow) * Hn + kc * 64 + u * 8;
    float v[8];
    float4 v0 = *reinterpret_cast<const float4*>(p);
    float4 v1 = *reinterpret_cast<const float4*>(p + 4);
    v[0] = v0.x; v[1] = v0.y; v[2] = v0.z; v[3] = v0.w;
    v[4] = v1.x; v[5] = v1.y; v[6] = v1.z; v[7] = v1.w;
    split8_g(&g_wih_h[(size_t)g * 8], &g_wih_l[(size_t)g * 8], v);
}

__global__ void k_prep_w(const float* __restrict__ We, const float* __restrict__ Wt) {
    int g = blockIdx.x * blockDim.x + threadIdx.x;    // 2048 units (grid 8 x 256)
    const float* W = blockIdx.y ? Wt : We;
    __nv_bfloat16* gh = blockIdx.y ? g_wt_h : g_we_h;
    __nv_bfloat16* gl = blockIdx.y ? g_wt_l : g_we_l;
    int kc = g >> 10, t = g & 1023;
    int row = t >> 3, u = t & 7;
    const float* p = W + (size_t)row * Hn + kc * 64 + u * 8;
    float v[8];
    float4 v0 = *reinterpret_cast<const float4*>(p);
    float4 v1 = *reinterpret_cast<const float4*>(p + 4);
    v[0] = v0.x; v[1] = v0.y; v[2] = v0.z; v[3] = v0.w;
    v[4] = v1.x; v[5] = v1.y; v[6] = v1.z; v[7] = v1.w;
    split8_g(&gh[(size_t)g * 8], &gl[(size_t)g * 8], v);
}

// ==================== k_lstm: 64-row tile, 3 CTAs/SM ====================
// grid(Bn/64, An)
__global__ __launch_bounds__(256, 3)
void k_lstm(const float* __restrict__ obs, const float* __restrict__ cv,
            const float* __restrict__ be, float* __restrict__ h1,
            float* __restrict__ c1, const float* __restrict__ Wg,
            const float* __restrict__ c0) {
    extern __shared__ char sm[];
    float* stage = (float*)(sm + L_BH);        // 16 KB stage aliases B-hi tile
    float* mi = (float*)(sm + L_MISC);
    float* s_bias = mi;            // 512
    float* s_c0   = mi + 512;      // 128
    float* s_wg   = mi + 640;      // 256

    const int tid = threadIdx.x, wid = tid >> 5, lane = tid & 31;
    const int m0 = blockIdx.x * 64;
    const int z  = blockIdx.y;
    const uint32_t sb = smem_u32(sm);
    const int wm = (wid & 3) * 16, wn = (wid >> 2) * 64;

    for (int i = tid; i < 512; i += 256) s_bias[i] = g_hh[z * G4 + i];
    if (tid < 128) s_c0[tid] = c0[z * Hn + tid];
    if (tid < 256) s_wg[tid] = Wg[z * 256 + tid];

    // ---------- phase 1: enc tile = obs_slice @ We^T (64 x 128) ----------
    const float* obs_s = obs + ((size_t)m0 * An + z) * Hn;
    float acc[1][8][4];
    ZERO_ACC_N(acc, 1);
    #pragma unroll 1
    for (int kc = 0; kc < 2; kc++) {
        if (kc) __syncthreads();
        load_tile<64>(sm, L_AH, L_AL, obs_s, An * Hn, kc * 64, tid);
        copy_tile(sm, L_BH, L_BL, g_we_h + kc * 8192, g_we_l + kc * 8192, tid);
        __syncthreads();
        mma_chunk<false, 1>(sb, L_AH, L_AL, L_BH, L_BL, 0, wm, wn, lane, acc);
    }

    // ---------- phase 2: + be + cv, split into resident full-K A tiles ----------
    #pragma unroll 1
    for (int ph = 0; ph < 2; ph++) {
        __syncthreads();
        stage_half<1>(stage, wm, wn, ph, lane, acc);
        __syncthreads();
        #pragma unroll
        for (int i = 0; i < 2; i++) {
            int idx = tid + i * 256;           // 512: 64 rows x 8 units
            int row = idx >> 3, u = idx & 7;
            int cb = ph * 64 + u * 8;
            const float* sp = &stage[sidx(row, u * 8)];
            const float* cp = cv + ((size_t)(m0 + row) * An + z) * Hn + cb;
            float v[8];
            #pragma unroll
            for (int j = 0; j < 8; j += 4) {
                float4 sv = *reinterpret_cast<const float4*>(sp + j);
                float4 bv = *reinterpret_cast<const float4*>(be + cb + j);
                float4 cvv = *reinterpret_cast<const float4*>(cp + j);
                v[j + 0] = sv.x + bv.x + cvv.x;
                v[j + 1] = sv.y + bv.y + cvv.y;
                v[j + 2] = sv.z + bv.z + cvv.z;
                v[j + 3] = sv.w + bv.w + cvv.w;
            }
            split8(sm, L_AH, L_AL, suA(row, ph * 8 + u), v);
        }
    }

    // ---------- phase 3: gates GEMM + LSTM epilogue ----------
    #pragma unroll 1
    for (int nc = 0; nc < 4; nc++) {
        ZERO_ACC_N(acc, 1);
        #pragma unroll 1
        for (int kc = 0; kc < 2; kc++) {
            __syncthreads();
            {
                size_t base = ((size_t)(z * 4 + nc) * 2 + kc) << 13;   // *8192 elems
                copy_tile(sm, L_BH, L_BL, g_wih_h + base, g_wih_l + base, tid);
            }
            __syncthreads();
            mma_chunk<true, 1>(sb, L_AH, L_AL, L_BH, L_BL, kc, wm, wn, lane, acc);
        }
        #pragma unroll 1
        for (int ph = 0; ph < 2; ph++) {
            __syncthreads();
            stage_half<1>(stage, wm, wn, ph, lane, acc);
            __syncthreads();
            #pragma unroll
            for (int i = 0; i < 4; i++) {
                int idx = tid + i * 256;       // 1024: 64 rows x 16 hl
                int r = idx >> 4, hl = idx & 15;
                float4 g = *reinterpret_cast<float4*>(&stage[sidx(r, 4 * hl)]);
                int gb = nc * 128 + ph * 64 + 4 * hl;
                int h = nc * 32 + ph * 16 + hl;
                float ig = g.x + s_bias[gb + 0];
                float fg = g.y + s_bias[gb + 1];
                float gg = g.z + s_bias[gb + 2];
                float og = g.w + s_bias[gb + 3];
                float cc = fsig(fg) * s_c0[h] + fsig(ig) * ftanh(gg);
                float hv = fsig(og) * ftanh(cc);
                size_t off = ((size_t)(m0 + r) * An + z) * 128 + h;
                h1[off] = hv;
                c1[off] = cc;
                float p0 = hv * s_wg[h];
                float p1 = hv * s_wg[128 + h];
                #pragma unroll
                for (int o = 8; o; o >>= 1) {
                    p0 += __shfl_xor_sync(0xFFFFFFFFu, p0, o);
                    p1 += __shfl_xor_sync(0xFFFFFFFFu, p1, o);
                }
                if ((lane & 15) == 0)
                    *reinterpret_cast<float2*>(
                        &g_logp[(((size_t)z * Bn) + (m0 + r)) * 16 + nc * 4 + ph * 2]) =
                        make_float2(p0, p1);
            }
        }
    }
}

// ==================== k_amax ====================
__global__ __launch_bounds__(256)
void k_amax(const float* __restrict__ bg) {
    __shared__ unsigned long long sred[8];
    const int a = blockIdx.x, j = blockIdx.y;
    const int tid = threadIdx.x, wid = tid >> 5, lane = tid & 31;
    float b0 = bg[a * 2 + 0], b1 = bg[a * 2 + 1];
    unsigned long long best = 0ull;
    #pragma unroll
    for (int i = 0; i < 4; i++) {
        int b = j * 1024 + i * 256 + tid;
        const float4* lp = reinterpret_cast<const float4*>(
            &g_logp[((size_t)a * Bn + b) * 16]);
        float4 q0 = lp[0], q1 = lp[1], q2 = lp[2], q3 = lp[3];
        float l0 = ((q0.x + q0.z) + (q1.x + q1.z)) + ((q2.x + q2.z) + (q3.x + q3.z)) + b0;
        float l1 = ((q0.y + q0.w) + (q1.y + q1.w)) + ((q2.y + q2.w) + (q3.y + q3.w)) + b1;
        float d = l0 - l1;
        float p = 1.0f / (1.0f + expf(-fabsf(d)));
        unsigned pidx = 2u * (unsigned)b + (d >= 0.f ? 0u : 1u);
        unsigned long long packed =
            ((unsigned long long)__float_as_uint(p) << 32) | (0xFFFFFFFFu - pidx);
        if (packed > best) best = packed;
    }
    #pragma unroll
    for (int o = 16; o; o >>= 1) {
        unsigned long long other = __shfl_xor_sync(0xFFFFFFFFu, best, o);
        if (other > best) best = other;
    }
    if (lane == 0) sred[wid] = best;
    __syncthreads();
    if (tid == 0) {
        unsigned long long m = sred[0];
        #pragma unroll
        for (int i = 1; i < 8; i++) if (sred[i] > m) m = sred[i];
        atomicMax(&g_argmax[a], m);
    }
}

// ==================== k_out ====================
__global__ __launch_bounds__(256, 2)
void k_out(const float* __restrict__ h1, float* __restrict__ out,
           const float* __restrict__ bt, const int* __restrict__ alive) {
    extern __shared__ char sm[];
    float* stage = (float*)sm;
    float* mi = (float*)(sm + OF_MISC);
    float* sidxv = mi;             // 32
    float* scs   = mi + 32;        // 512

    const int tid = threadIdx.x, wid = tid >> 5, lane = tid & 31;
    const int m0 = blockIdx.x * 128;
    const uint32_t sb = smem_u32(sm);
    const int wm = (wid & 3) * 32, wn = (wid >> 2) * 64;

    if (tid < 32)
        sidxv[tid] = (float)(0xFFFFFFFFu - (unsigned)(g_argmax[tid] & 0xFFFFFFFFull));
    __syncthreads();

    {
        int v = alive ? *alive : An;
        if (v < 0 || v > (1 << 20)) v = (int)__int_as_float(v);
        float norm = v ? 1.0f / (float)(v - 1) : 1.0f;
        #pragma unroll 1
        for (int t = tid; t < 512; t += 256) {
            int bl = t >> 7, h = t & 127;
            const float* hp = h1 + (size_t)(m0 + bl * 32) * 128 + h;
            float s = 0.f;
            #pragma unroll
            for (int a = 0; a < An; a++) s += sidxv[a] * hp[a * 128];
            scs[bl * 128 + h] = norm * s;
        }
    }
    __syncthreads();

    float acc[2][8][4];
    ZERO_ACC_N(acc, 2);
    for (int kc = 0; kc < 2; kc++) {
        #pragma unroll
        for (int i = 0; i < 4; i++) {
            int idx = tid + i * 256;
            int row = idx >> 3, u = idx & 7;
            int bl = row >> 5, a = row & 31;
            float ia = sidxv[a];
            const float* p = h1 + (size_t)(m0 + row) * 128 + kc * 64 + u * 8;
            float v[8];
            float4 v0 = *reinterpret_cast<const float4*>(p);
            float4 v1 = *reinterpret_cast<const float4*>(p + 4);
            const float* sc = &scs[bl * 128 + kc * 64 + u * 8];
            v[0] = sc[0] - ia * v0.x; v[1] = sc[1] - ia * v0.y;
            v[2] = sc[2] - ia * v0.z; v[3] = sc[3] - ia * v0.w;
            v[4] = sc[4] - ia * v1.x; v[5] = sc[5] - ia * v1.y;
            v[6] = sc[6] - ia * v1.z; v[7] = sc[7] - ia * v1.w;
            split8(sm, OF_AH, OF_AL, su(row, u), v);
        }
        copy_tile(sm, OF_BH, OF_BL, g_wt_h + kc * 8192, g_wt_l + kc * 8192, tid);
        __syncthreads();
        mma_chunk<false, 2>(sb, OF_AH, OF_AL, OF_BH, OF_BL, 0, wm, wn, lane, acc);
        __syncthreads();
    }
    stage_acc(stage, wm, wn, lane, acc);
    __syncthreads();

    #pragma unroll 1
    for (int rr = 0; rr < 16; rr++) {
        int r = wid * 16 + rr;
        float v[4];
        #pragma unroll
        for (int j = 0; j < 4; j++)
            v[j] = stage[r * 132 + lane * 4 + j] + bt[lane * 4 + j];
        float mx = fmaxf(fmaxf(v[0], v[1]), fmaxf(v[2], v[3]));
        #pragma unroll
        for (int o = 16; o; o >>= 1)
            mx = fmaxf(mx, __shfl_xor_sync(0xFFFFFFFFu, mx, o));
        float s = 0.f;
        #pragma unroll
        for (int j = 0; j < 4; j++) { v[j] = __expf(v[j] - mx); s += v[j]; }
        #pragma unroll
        for (int o = 16; o; o >>= 1)
            s += __shfl_xor_sync(0xFFFFFFFFu, s, o);
        float inv = __fdividef(1.0f, s);
        float4 o4 = make_float4(v[0] * inv, v[1] * inv, v[2] * inv, v[3] * inv);
        *reinterpret_cast<float4*>(out + (size_t)(m0 + r) * 128 + lane * 4) = o4;
    }
}

// ==================== k_hh (prep) ====================
__global__ void k_hh(const float* __restrict__ h0, const float* __restrict__ Whh,
                     const float* __restrict__ bih, const float* __restrict__ bhh) {
    if (blockIdx.x == 0 && threadIdx.x < An) g_argmax[threadIdx.x] = 0ull;
    int w = (blockIdx.x * blockDim.x + threadIdx.x) >> 5;
    int lane = threadIdx.x & 31;
    if (w >= An * G4) return;
    int a = w / G4;
    float4 hv = *reinterpret_cast<const float4*>(h0 + a * Hn + lane * 4);
    float4 wv = *reinterpret_cast<const float4*>(Whh + (size_t)w * Hn + lane * 4);
    float s = hv.x * wv.x + hv.y * wv.y + hv.z * wv.z + hv.w * wv.w;
    #pragma unroll
    for (int off = 16; off; off >>= 1) s += __shfl_xor_sync(0xFFFFFFFFu, s, off);
    if (lane == 0) {
        int gsrc = w % G4;
        int gate = gsrc >> 7, h = gsrc & 127;
        g_hh[a * G4 + 4 * h + gate] = s + bih[w] + bhh[w];
    }
}

// ==================== launch ====================
extern "C" void kernel_launch(void* const* d_in, const int* in_sizes, int n_in,
                              void* d_out, int out_size) {
    const float* obs = (const float*)d_in[0];
    const float* cv  = (const float*)d_in[1];
    const float* h0  = (const float*)d_in[2];
    const float* c0  = (const float*)d_in[3];
    const float* We  = (const float*)d_in[4];
    const float* be  = (const float*)d_in[5];
    const float* Wih = (const float*)d_in[6];
    const float* Whh = (const float*)d_in[7];
    const float* bih = (const float*)d_in[8];
    const float* bhh = (const float*)d_in[9];
    const float* Wg  = (const float*)d_in[10];
    const float* bg  = (const float*)d_in[11];
    const float* Wt  = (const float*)d_in[12];
    const float* bt  = (const float*)d_in[13];
    const int* alive = (n_in > 14) ? (const int*)d_in[14] : nullptr;
    float* dout = (float*)d_out;

    cudaFuncSetAttribute(k_lstm, cudaFuncAttributeMaxDynamicSharedMemorySize, SMEM_L);
    cudaFuncSetAttribute(k_out,  cudaFuncAttributeMaxDynamicSharedMemorySize, SMEM_G);

    k_hh<<<2048, 256>>>(h0, Whh, bih, bhh);
    k_prep_wih<<<1024, 256>>>(Wih);
    k_prep_w<<<dim3(8, 2), 256>>>(We, Wt);

    // 64-row tiles: grid (64, 32), 3 CTAs/SM
    k_lstm<<<dim3(Bn / 64, An), 256, SMEM_L>>>(obs, cv, be, dout + BAH,
                                               dout + 2 * BAH, Wg, c0);

    k_amax<<<dim3(An, 4), 256>>>(bg);

    k_out<<<M_BIG / 128, 256, SMEM_G>>>(dout + BAH, dout, bt, alive);
}

// round 16
// speedup vs baseline: 1.0961x; 1.0961x over previous
#include <cuda_runtime.h>
#include <cuda_bf16.h>
#include <cuda_pipeline.h>
#include <math.h>
#include <stdint.h>

// Problem constants
constexpr int Bn = 4096;
constexpr int An = 32;
constexpr int Hn = 128;
constexpr int G4 = 4 * Hn;          // 512
constexpr int M_BIG = Bn * An;      // 131072
constexpr int BAH = Bn * An * Hn;   // 16,777,216

// -------------------- scratch --------------------
__device__ float g_hh[An * G4];                // interleaved (4h+gate) hidden bias
__device__ float g_logp[(size_t)An * Bn * 16]; // logit partials (8 MB)
__device__ unsigned long long g_argmax[An];
// pre-split weights (hi/lo bf16, chunk-linear 16B units)
__device__ __nv_bfloat16 g_wih_h[An * G4 * Hn];   // 4 MB, permuted gate layout
__device__ __nv_bfloat16 g_wih_l[An * G4 * Hn];
__device__ __nv_bfloat16 g_we_h[Hn * Hn], g_we_l[Hn * Hn];
__device__ __nv_bfloat16 g_wt_h[Hn * Hn], g_wt_l[Hn * Hn];

// ==================== helpers ====================
__device__ __forceinline__ uint32_t smem_u32(const void* p) {
    uint32_t a;
    asm("{ .reg .u64 t; cvta.to.shared.u64 t, %1; cvt.u32.u64 %0, t; }"
        : "=r"(a) : "l"(p));
    return a;
}
__device__ __forceinline__ uint32_t pk(float k0, float k1) {
    uint32_t r;
    asm("cvt.rn.satfinite.bf16x2.f32 %0, %1, %2;" : "=r"(r) : "f"(k1), "f"(k0));
    return r;
}
__device__ __forceinline__ void ldsm_x4(uint32_t* r, uint32_t addr) {
    asm volatile("ldmatrix.sync.aligned.m8n8.x4.shared.b16 {%0,%1,%2,%3}, [%4];"
                 : "=r"(r[0]), "=r"(r[1]), "=r"(r[2]), "=r"(r[3]) : "r"(addr));
}
__device__ __forceinline__ void mma_bf16(float* d, const uint32_t* a, const uint32_t* b) {
    asm volatile(
        "mma.sync.aligned.m16n8k16.row.col.f32.bf16.bf16.f32 "
        "{%0,%1,%2,%3}, {%4,%5,%6,%7}, {%8,%9}, {%0,%1,%2,%3};"
        : "+f"(d[0]), "+f"(d[1]), "+f"(d[2]), "+f"(d[3])
        : "r"(a[0]), "r"(a[1]), "r"(a[2]), "r"(a[3]), "r"(b[0]), "r"(b[1]));
}
// fast transcendentals (MUFU-based); error ~1e-6 << bf16-split noise ~1e-4
__device__ __forceinline__ float fsig(float x) {
    return __fdividef(1.0f, 1.0f + __expf(-x));
}
__device__ __forceinline__ float ftanh(float x) {
    float t = __expf(-2.0f * x);
    return __fdividef(1.0f - t, 1.0f + t);
}

// -------------------- SMEM layouts (round-14 sizing) --------------------
constexpr int OF_AH = 0;
constexpr int OF_AL = 16384;
constexpr int OF_BH = 32768;
constexpr int OF_BL = 49152;           // tiles end 65536
constexpr int OF_MISC = 69632;         // stage (128x132 f32) aliases tiles
constexpr int SMEM_G = 72192;

constexpr int L_AH = 0;
constexpr int L_AL = 32768;
constexpr int L_BH = 65536;
constexpr int L_BL = 81920;            // tiles end 98304
constexpr int L_MISC = 98304;
constexpr int SMEM_L = 101888;         // 2 CTAs/SM

__device__ __forceinline__ uint32_t su(int row, int u) {
    return (uint32_t)(row * 128 + ((u ^ (row & 7)) << 4));
}
__device__ __forceinline__ uint32_t suA(int row, int u) {
    return (uint32_t)(row * 256 + (((u & 7) ^ (row & 7)) << 4) + ((u >> 3) << 7));
}
__device__ __forceinline__ int sidx(int r, int c) {
    return r * 64 + (c ^ ((r & 7) << 3));
}

// split 8 floats -> hi/lo bf16x2 quads at given swizzled byte offset
__device__ __forceinline__ void split8(char* sm, int hib, int lob, uint32_t off,
                                       const float* v) {
    float h[8];
    #pragma unroll
    for (int j = 0; j < 8; j++) h[j] = __bfloat162float(__float2bfloat16(v[j]));
    uint4 hi = make_uint4(pk(v[0], v[1]), pk(v[2], v[3]), pk(v[4], v[5]), pk(v[6], v[7]));
    uint4 lo = make_uint4(pk(v[0] - h[0], v[1] - h[1]), pk(v[2] - h[2], v[3] - h[3]),
                          pk(v[4] - h[4], v[5] - h[5]), pk(v[6] - h[6], v[7] - h[7]));
    *reinterpret_cast<uint4*>(sm + hib + off) = hi;
    *reinterpret_cast<uint4*>(sm + lob + off) = lo;
}

// split 8 floats into two global uint4 slots (for weight prep)
__device__ __forceinline__ void split8_g(__nv_bfloat16* gh, __nv_bfloat16* gl,
                                         const float* v) {
    float h[8];
    #pragma unroll
    for (int j = 0; j < 8; j++) h[j] = __bfloat162float(__float2bfloat16(v[j]));
    uint4 hi = make_uint4(pk(v[0], v[1]), pk(v[2], v[3]), pk(v[4], v[5]), pk(v[6], v[7]));
    uint4 lo = make_uint4(pk(v[0] - h[0], v[1] - h[1]), pk(v[2] - h[2], v[3] - h[3]),
                          pk(v[4] - h[4], v[5] - h[5]), pk(v[6] - h[6], v[7] - h[7]));
    *reinterpret_cast<uint4*>(gh) = hi;
    *reinterpret_cast<uint4*>(gl) = lo;
}

// copy a pre-split 128x64 chunk (1024 16B units x2) into swizzled tiles
__device__ __forceinline__ void copy_tile(char* sm, int hib, int lob,
                                          const __nv_bfloat16* __restrict__ wh,
                                          const __nv_bfloat16* __restrict__ wl,
                                          int tid) {
    #pragma unroll
    for (int i = 0; i < 4; i++) {
        int idx = tid + i * 256;
        int row = idx >> 3, u = idx & 7;
        uint32_t off = su(row, u);
        *reinterpret_cast<uint4*>(sm + hib + off) =
            *reinterpret_cast<const uint4*>(wh + idx * 8);
        *reinterpret_cast<uint4*>(sm + lob + off) =
            *reinterpret_cast<const uint4*>(wl + idx * 8);
    }
}

// cp.async copy of ONE k-half (u = s*4 .. s*4+3) of a 128x64 pre-split chunk
// into the L_BH/L_BL tiles. 512 units per buffer; 2 hi + 2 lo per thread.
__device__ __forceinline__ void copy_half_async(char* sm,
                                                const __nv_bfloat16* __restrict__ wh,
                                                const __nv_bfloat16* __restrict__ wl,
                                                int tid, int s) {
    #pragma unroll
    for (int i = 0; i < 2; i++) {
        int idx = tid + i * 256;          // 512: row(128) x uu(4)
        int row = idx >> 2, uu = idx & 3;
        int u = s * 4 + uu;
        uint32_t off = su(row, u);
        int gsrc = (row * 8 + u) * 8;
        __pipeline_memcpy_async(sm + L_BH + off, wh + gsrc, 16);
        __pipeline_memcpy_async(sm + L_BL + off, wl + gsrc, 16);
    }
}

// load+split a 128x64 fp32 chunk into hi/lo chunk tiles (dynamic A only)
__device__ __forceinline__ void load_tile(char* sm, int hib, int lob,
                                          const float* __restrict__ src, int lda,
                                          int k0, int tid) {
    #pragma unroll
    for (int i = 0; i < 4; i++) {
        int idx = tid + i * 256;
        int row = idx >> 3, u = idx & 7;
        const float* p = src + (size_t)row * lda + k0 + u * 8;
        float v[8];
        float4 v0 = *reinterpret_cast<const float4*>(p);
        float4 v1 = *reinterpret_cast<const float4*>(p + 4);
        v[0] = v0.x; v[1] = v0.y; v[2] = v0.z; v[3] = v0.w;
        v[4] = v1.x; v[5] = v1.y; v[6] = v1.z; v[7] = v1.w;
        split8(sm, hib, lob, su(row, u), v);
    }
}

// 3-pass split MMA over one 64-K chunk; A (hi+lo) register-resident per ks.
// Per-accumulator pass order: hh, lh, hl (bit-identical across rounds).
template <bool AFULL>
__device__ __forceinline__ void mma_chunk(uint32_t sb, int aHi, int aLo, int bHi,
                                          int bLo, int kcA, int wm, int wn, int lane,
                                          float acc[2][8][4]) {
    const int arow = (lane & 7) + ((lane >> 3) & 1) * 8;
    const int akq  = lane >> 4;
    const int bnt  = (lane >> 4) & 1;
    const int bkq  = (lane >> 3) & 1;
    const int brow = lane & 7;
    #pragma unroll
    for (int ks = 0; ks < 4; ks++) {
        uint32_t aH[2][4], aL[2][4], b[4][2];
        const int uA = (AFULL ? kcA * 8 : 0) + ks * 2 + akq;
        const int uB = ks * 2 + bkq;
        #pragma unroll
        for (int mt = 0; mt < 2; mt++) {
            int r = wm + mt * 16 + arow;
            uint32_t offA = AFULL ? suA(r, uA) : su(r, uA);
            ldsm_x4(aH[mt], sb + aHi + offA);
            ldsm_x4(aL[mt], sb + aLo + offA);
        }
        #pragma unroll
        for (int hf = 0; hf < 2; hf++) {
            #pragma unroll
            for (int nt2 = 0; nt2 < 4; nt2 += 2)
                ldsm_x4(&b[nt2][0],
                        sb + bHi + su(wn + (hf * 4 + nt2 + bnt) * 8 + brow, uB));
            #pragma unroll
            for (int mt = 0; mt < 2; mt++)
                #pragma unroll
                for (int nt = 0; nt < 4; nt++)
                    mma_bf16(acc[mt][hf * 4 + nt], aH[mt], b[nt]);
            #pragma unroll
            for (int mt = 0; mt < 2; mt++)
                #pragma unroll
                for (int nt = 0; nt < 4; nt++)
                    mma_bf16(acc[mt][hf * 4 + nt], aL[mt], b[nt]);
            #pragma unroll
            for (int nt2 = 0; nt2 < 4; nt2 += 2)
                ldsm_x4(&b[nt2][0],
                        sb + bLo + su(wn + (hf * 4 + nt2 + bnt) * 8 + brow, uB));
            #pragma unroll
            for (int mt = 0; mt < 2; mt++)
                #pragma unroll
                for (int nt = 0; nt < 4; nt++)
                    mma_bf16(acc[mt][hf * 4 + nt], aH[mt], b[nt]);
        }
    }
}

// same as mma_chunk<true> but only the two ks of k-half s (identical per-acc order)
__device__ __forceinline__ void mma_half(uint32_t sb, int kcA, int s, int wm, int wn,
                                         int lane, float acc[2][8][4]) {
    const int arow = (lane & 7) + ((lane >> 3) & 1) * 8;
    const int akq  = lane >> 4;
    const int bnt  = (lane >> 4) & 1;
    const int bkq  = (lane >> 3) & 1;
    const int brow = lane & 7;
    #pragma unroll
    for (int j = 0; j < 2; j++) {
        int ks = s * 2 + j;
        uint32_t aH[2][4], aL[2][4], b[4][2];
        const int uA = kcA * 8 + ks * 2 + akq;
        const int uB = ks * 2 + bkq;
        #pragma unroll
        for (int mt = 0; mt < 2; mt++) {
            int r = wm + mt * 16 + arow;
            uint32_t offA = suA(r, uA);
            ldsm_x4(aH[mt], sb + L_AH + offA);
            ldsm_x4(aL[mt], sb + L_AL + offA);
        }
        #pragma unroll
        for (int hf = 0; hf < 2; hf++) {
            #pragma unroll
            for (int nt2 = 0; nt2 < 4; nt2 += 2)
                ldsm_x4(&b[nt2][0],
                        sb + L_BH + su(wn + (hf * 4 + nt2 + bnt) * 8 + brow, uB));
            #pragma unroll
            for (int mt = 0; mt < 2; mt++)
                #pragma unroll
                for (int nt = 0; nt < 4; nt++)
                    mma_bf16(acc[mt][hf * 4 + nt], aH[mt], b[nt]);
            #pragma unroll
            for (int mt = 0; mt < 2; mt++)
                #pragma unroll
                for (int nt = 0; nt < 4; nt++)
                    mma_bf16(acc[mt][hf * 4 + nt], aL[mt], b[nt]);
            #pragma unroll
            for (int nt2 = 0; nt2 < 4; nt2 += 2)
                ldsm_x4(&b[nt2][0],
                        sb + L_BL + su(wn + (hf * 4 + nt2 + bnt) * 8 + brow, uB));
            #pragma unroll
            for (int mt = 0; mt < 2; mt++)
                #pragma unroll
                for (int nt = 0; nt < 4; nt++)
                    mma_bf16(acc[mt][hf * 4 + nt], aH[mt], b[nt]);
        }
    }
}

__device__ __forceinline__ void stage_acc(float* stage, int wm, int wn, int lane,
                                          float acc[2][8][4]) {
    const int grp = lane >> 2, qp = lane & 3;
    #pragma unroll
    for (int mt = 0; mt < 2; mt++)
        #pragma unroll
        for (int nt = 0; nt < 8; nt++) {
            int r = wm + mt * 16 + grp;
            int c = wn + nt * 8 + qp * 2;
            stage[r * 132 + c] = acc[mt][nt][0];
            stage[r * 132 + c + 1] = acc[mt][nt][1];
            stage[(r + 8) * 132 + c] = acc[mt][nt][2];
            stage[(r + 8) * 132 + c + 1] = acc[mt][nt][3];
        }
}

__device__ __forceinline__ void stage_half(float* stage, int wm, int wn, int ph,
                                           int lane, float acc[2][8][4]) {
    if (wn == ph * 64) {
        const int grp = lane >> 2, qp = lane & 3;
        #pragma unroll
        for (int mt = 0; mt < 2; mt++)
            #pragma unroll
            for (int nt = 0; nt < 8; nt++) {
                int r = wm + mt * 16 + grp;
                int c = nt * 8 + qp * 2;
                *reinterpret_cast<float2*>(&stage[sidx(r, c)]) =
                    make_float2(acc[mt][nt][0], acc[mt][nt][1]);
                *reinterpret_cast<float2*>(&stage[sidx(r + 8, c)]) =
                    make_float2(acc[mt][nt][2], acc[mt][nt][3]);
            }
    }
}

#define ZERO_ACC(acc)                                                     \
    _Pragma("unroll") for (int mt = 0; mt < 2; mt++)                      \
        _Pragma("unroll") for (int nt = 0; nt < 8; nt++)                  \
            _Pragma("unroll") for (int e = 0; e < 4; e++) acc[mt][nt][e] = 0.f;

// ==================== prep: split weights ====================
__global__ void k_prep_wih(const float* __restrict__ Wih) {
    int g = blockIdx.x * blockDim.x + threadIdx.x;    // 262144 units
    int z = g >> 13, r = g & 8191;
    int nc = r >> 11, r2 = r & 2047;
    int kc = r2 >> 10, t = r2 & 1023;
    int row = t >> 3, u = t & 7;
    int ng = nc * 128 + row;
    int srow = (ng & 3) * 128 + (ng >> 2);
    const float* p = Wih + ((size_t)z * G4 + srow) * Hn + kc * 64 + u * 8;
    float v[8];
    float4 v0 = *reinterpret_cast<const float4*>(p);
    float4 v1 = *reinterpret_cast<const float4*>(p + 4);
    v[0] = v0.x; v[1] = v0.y; v[2] = v0.z; v[3] = v0.w;
    v[4] = v1.x; v[5] = v1.y; v[6] = v1.z; v[7] = v1.w;
    split8_g(&g_wih_h[(size_t)g * 8], &g_wih_l[(size_t)g * 8], v);
}

__global__ void k_prep_w(const float* __restrict__ We, const float* __restrict__ Wt) {
    int g = blockIdx.x * blockDim.x + threadIdx.x;    // 2048 units (grid 8 x 256)
    const float* W = blockIdx.y ? Wt : We;
    __nv_bfloat16* gh = blockIdx.y ? g_wt_h : g_we_h;
    __nv_bfloat16* gl = blockIdx.y ? g_wt_l : g_we_l;
    int kc = g >> 10, t = g & 1023;
    int row = t >> 3, u = t & 7;
    const float* p = W + (size_t)row * Hn + kc * 64 + u * 8;
    float v[8];
    float4 v0 = *reinterpret_cast<const float4*>(p);
    float4 v1 = *reinterpret_cast<const float4*>(p + 4);
    v[0] = v0.x; v[1] = v0.y; v[2] = v0.z; v[3] = v0.w;
    v[4] = v1.x; v[5] = v1.y; v[6] = v1.z; v[7] = v1.w;
    split8_g(&gh[(size_t)g * 8], &gl[(size_t)g * 8], v);
}

// ==================== k_lstm: fused enc+gates+LSTM, cp.async-pipelined B ====================
// grid(Bn/128, An), 2 CTAs/SM
__global__ __launch_bounds__(256, 2)
void k_lstm(const float* __restrict__ obs, const float* __restrict__ cv,
            const float* __restrict__ be, float* __restrict__ h1,
            float* __restrict__ c1, const float* __restrict__ Wg,
            const float* __restrict__ c0) {
    extern __shared__ char sm[];
    float* stage = (float*)(sm + L_BH);        // 32 KB stage aliases B tiles
    float* mi = (float*)(sm + L_MISC);
    float* s_bias = mi;            // 512
    float* s_c0   = mi + 512;      // 128
    float* s_wg   = mi + 640;      // 256

    const int tid = threadIdx.x, wid = tid >> 5, lane = tid & 31;
    const int m0 = blockIdx.x * 128;
    const int z  = blockIdx.y;
    const uint32_t sb = smem_u32(sm);
    const int wm = (wid & 3) * 32, wn = (wid >> 2) * 64;

    for (int i = tid; i < 512; i += 256) s_bias[i] = g_hh[z * G4 + i];
    if (tid < 128) s_c0[tid] = c0[z * Hn + tid];
    if (tid < 256) s_wg[tid] = Wg[z * 256 + tid];

    // ---------- phase 1: enc tile = obs_slice @ We^T ----------
    const float* obs_s = obs + ((size_t)m0 * An + z) * Hn;
    float acc[2][8][4];
    ZERO_ACC(acc);
    #pragma unroll 1
    for (int kc = 0; kc < 2; kc++) {
        if (kc) __syncthreads();
        load_tile(sm, L_AH, L_AL, obs_s, An * Hn, kc * 64, tid);
        copy_tile(sm, L_BH, L_BL, g_we_h + kc * 8192, g_we_l + kc * 8192, tid);
        __syncthreads();
        mma_chunk<false>(sb, L_AH, L_AL, L_BH, L_BL, 0, wm, wn, lane, acc);
    }

    // ---------- phase 2: + be + cv, split into resident full-K A tiles ----------
    #pragma unroll 1
    for (int ph = 0; ph < 2; ph++) {
        __syncthreads();
        stage_half(stage, wm, wn, ph, lane, acc);
        __syncthreads();
        #pragma unroll
        for (int i = 0; i < 4; i++) {
            int idx = tid + i * 256;
            int row = idx >> 3, u = idx & 7;
            int cb = ph * 64 + u * 8;
            const float* sp = &stage[sidx(row, u * 8)];
            const float* cp = cv + ((size_t)(m0 + row) * An + z) * Hn + cb;
            float v[8];
            #pragma unroll
            for (int j = 0; j < 8; j += 4) {
                float4 sv = *reinterpret_cast<const float4*>(sp + j);
                float4 bv = *reinterpret_cast<const float4*>(be + cb + j);
                float4 cvv = *reinterpret_cast<const float4*>(cp + j);
                v[j + 0] = sv.x + bv.x + cvv.x;
                v[j + 1] = sv.y + bv.y + cvv.y;
                v[j + 2] = sv.z + bv.z + cvv.z;
                v[j + 3] = sv.w + bv.w + cvv.w;
            }
            split8(sm, L_AH, L_AL, suA(row, ph * 8 + u), v);
        }
    }

    // ---------- phase 3: gates GEMM (pipelined B) + LSTM epilogue ----------
    #pragma unroll 1
    for (int nc = 0; nc < 4; nc++) {
        ZERO_ACC(acc);
        __syncthreads();   // prior stage/epilogue (or phase-2) reads of B region done
        // prime the pipe: (kc=0, s=0)
        {
            size_t base = ((size_t)(z * 4 + nc) * 2 + 0) << 13;
            copy_half_async(sm, g_wih_h + base, g_wih_l + base, tid, 0);
            __pipeline_commit();
        }
        #pragma unroll 1
        for (int t = 0; t < 4; t++) {
            int kc = t >> 1, s = t & 1;
            __pipeline_wait_prior(0);
            __syncthreads();           // half t in smem everywhere; mma(t-1) done
            if (t < 3) {
                int t2 = t + 1;
                size_t base = ((size_t)(z * 4 + nc) * 2 + (t2 >> 1)) << 13;
                copy_half_async(sm, g_wih_h + base, g_wih_l + base, tid, t2 & 1);
                __pipeline_commit();
            }
            mma_half(sb, kc, s, wm, wn, lane, acc);
        }
        // epilogue in two 64-col halves (stage aliases B region; pipe drained)
        #pragma unroll 1
        for (int ph = 0; ph < 2; ph++) {
            __syncthreads();
            stage_half(stage, wm, wn, ph, lane, acc);
            __syncthreads();
            #pragma unroll
            for (int i = 0; i < 8; i++) {
                int idx = tid + i * 256;       // 2048: 128 rows x 16 hl
                int r = idx >> 4, hl = idx & 15;
                float4 g = *reinterpret_cast<float4*>(&stage[sidx(r, 4 * hl)]);
                int gb = nc * 128 + ph * 64 + 4 * hl;
                int h = nc * 32 + ph * 16 + hl;
                float ig = g.x + s_bias[gb + 0];
                float fg = g.y + s_bias[gb + 1];
                float gg = g.z + s_bias[gb + 2];
                float og = g.w + s_bias[gb + 3];
                float cc = fsig(fg) * s_c0[h] + fsig(ig) * ftanh(gg);
                float hv = fsig(og) * ftanh(cc);
                size_t off = ((size_t)(m0 + r) * An + z) * 128 + h;
                h1[off] = hv;
                c1[off] = cc;
                float p0 = hv * s_wg[h];
                float p1 = hv * s_wg[128 + h];
                #pragma unroll
                for (int o = 8; o; o >>= 1) {
                    p0 += __shfl_xor_sync(0xFFFFFFFFu, p0, o);
                    p1 += __shfl_xor_sync(0xFFFFFFFFu, p1, o);
                }
                if ((lane & 15) == 0)
                    *reinterpret_cast<float2*>(
                        &g_logp[(((size_t)z * Bn) + (m0 + r)) * 16 + nc * 4 + ph * 2]) =
                        make_float2(p0, p1);
            }
        }
    }
}

// ==================== k_amax ====================
__global__ __launch_bounds__(256)
void k_amax(const float* __restrict__ bg) {
    __shared__ unsigned long long sred[8];
    const int a = blockIdx.x, j = blockIdx.y;
    const int tid = threadIdx.x, wid = tid >> 5, lane = tid & 31;
    float b0 = bg[a * 2 + 0], b1 = bg[a * 2 + 1];
    unsigned long long best = 0ull;
    #pragma unroll
    for (int i = 0; i < 4; i++) {
        int b = j * 1024 + i * 256 + tid;
        const float4* lp = reinterpret_cast<const float4*>(
            &g_logp[((size_t)a * Bn + b) * 16]);
        float4 q0 = lp[0], q1 = lp[1], q2 = lp[2], q3 = lp[3];
        float l0 = ((q0.x + q0.z) + (q1.x + q1.z)) + ((q2.x + q2.z) + (q3.x + q3.z)) + b0;
        float l1 = ((q0.y + q0.w) + (q1.y + q1.w)) + ((q2.y + q2.w) + (q3.y + q3.w)) + b1;
        float d = l0 - l1;
        float p = 1.0f / (1.0f + expf(-fabsf(d)));
        unsigned pidx = 2u * (unsigned)b + (d >= 0.f ? 0u : 1u);
        unsigned long long packed =
            ((unsigned long long)__float_as_uint(p) << 32) | (0xFFFFFFFFu - pidx);
        if (packed > best) best = packed;
    }
    #pragma unroll
    for (int o = 16; o; o >>= 1) {
        unsigned long long other = __shfl_xor_sync(0xFFFFFFFFu, best, o);
        if (other > best) best = other;
    }
    if (lane == 0) sred[wid] = best;
    __syncthreads();
    if (tid == 0) {
        unsigned long long m = sred[0];
        #pragma unroll
        for (int i = 1; i < 8; i++) if (sred[i] > m) m = sred[i];
        atomicMax(&g_argmax[a], m);
    }
}

// ==================== k_out ====================
__global__ __launch_bounds__(256, 2)
void k_out(const float* __restrict__ h1, float* __restrict__ out,
           const float* __restrict__ bt, const int* __restrict__ alive) {
    extern __shared__ char sm[];
    float* stage = (float*)sm;
    float* mi = (float*)(sm + OF_MISC);
    float* sidxv = mi;             // 32
    float* scs   = mi + 32;        // 512

    const int tid = threadIdx.x, wid = tid >> 5, lane = tid & 31;
    const int m0 = blockIdx.x * 128;
    const uint32_t sb = smem_u32(sm);
    const int wm = (wid & 3) * 32, wn = (wid >> 2) * 64;

    if (tid < 32)
        sidxv[tid] = (float)(0xFFFFFFFFu - (unsigned)(g_argmax[tid] & 0xFFFFFFFFull));
    __syncthreads();

    {
        int v = alive ? *alive : An;
        if (v < 0 || v > (1 << 20)) v = (int)__int_as_float(v);
        float norm = v ? 1.0f / (float)(v - 1) : 1.0f;
        #pragma unroll 1
        for (int t = tid; t < 512; t += 256) {
            int bl = t >> 7, h = t & 127;
            const float* hp = h1 + (size_t)(m0 + bl * 32) * 128 + h;
            float s = 0.f;
            #pragma unroll
            for (int a = 0; a < An; a++) s += sidxv[a] * hp[a * 128];
            scs[bl * 128 + h] = norm * s;
        }
    }
    __syncthreads();

    float acc[2][8][4];
    ZERO_ACC(acc);
    for (int kc = 0; kc < 2; kc++) {
        #pragma unroll
        for (int i = 0; i < 4; i++) {
            int idx = tid + i * 256;
            int row = idx >> 3, u = idx & 7;
            int bl = row >> 5, a = row & 31;
            float ia = sidxv[a];
            const float* p = h1 + (size_t)(m0 + row) * 128 + kc * 64 + u * 8;
            float v[8];
            float4 v0 = *reinterpret_cast<const float4*>(p);
            float4 v1 = *reinterpret_cast<const float4*>(p + 4);
            const float* sc = &scs[bl * 128 + kc * 64 + u * 8];
            v[0] = sc[0] - ia * v0.x; v[1] = sc[1] - ia * v0.y;
            v[2] = sc[2] - ia * v0.z; v[3] = sc[3] - ia * v0.w;
            v[4] = sc[4] - ia * v1.x; v[5] = sc[5] - ia * v1.y;
            v[6] = sc[6] - ia * v1.z; v[7] = sc[7] - ia * v1.w;
            split8(sm, OF_AH, OF_AL, su(row, u), v);
        }
        copy_tile(sm, OF_BH, OF_BL, g_wt_h + kc * 8192, g_wt_l + kc * 8192, tid);
        __syncthreads();
        mma_chunk<false>(sb, OF_AH, OF_AL, OF_BH, OF_BL, 0, wm, wn, lane, acc);
        __syncthreads();
    }
    stage_acc(stage, wm, wn, lane, acc);
    __syncthreads();

    #pragma unroll 1
    for (int rr = 0; rr < 16; rr++) {
        int r = wid * 16 + rr;
        float v[4];
        #pragma unroll
        for (int j = 0; j < 4; j++)
            v[j] = stage[r * 132 + lane * 4 + j] + bt[lane * 4 + j];
        float mx = fmaxf(fmaxf(v[0], v[1]), fmaxf(v[2], v[3]));
        #pragma unroll
        for (int o = 16; o; o >>= 1)
            mx = fmaxf(mx, __shfl_xor_sync(0xFFFFFFFFu, mx, o));
        float s = 0.f;
        #pragma unroll
        for (int j = 0; j < 4; j++) { v[j] = __expf(v[j] - mx); s += v[j]; }
        #pragma unroll
        for (int o = 16; o; o >>= 1)
            s += __shfl_xor_sync(0xFFFFFFFFu, s, o);
        float inv = __fdividef(1.0f, s);
        float4 o4 = make_float4(v[0] * inv, v[1] * inv, v[2] * inv, v[3] * inv);
        *reinterpret_cast<float4*>(out + (size_t)(m0 + r) * 128 + lane * 4) = o4;
    }
}

// ==================== k_hh (prep) ====================
__global__ void k_hh(const float* __restrict__ h0, const float* __restrict__ Whh,
                     const float* __restrict__ bih, const float* __restrict__ bhh) {
    if (blockIdx.x == 0 && threadIdx.x < An) g_argmax[threadIdx.x] = 0ull;
    int w = (blockIdx.x * blockDim.x + threadIdx.x) >> 5;
    int lane = threadIdx.x & 31;
    if (w >= An * G4) return;
    int a = w / G4;
    float4 hv = *reinterpret_cast<const float4*>(h0 + a * Hn + lane * 4);
    float4 wv = *reinterpret_cast<const float4*>(Whh + (size_t)w * Hn + lane * 4);
    float s = hv.x * wv.x + hv.y * wv.y + hv.z * wv.z + hv.w * wv.w;
    #pragma unroll
    for (int off = 16; off; off >>= 1) s += __shfl_xor_sync(0xFFFFFFFFu, s, off);
    if (lane == 0) {
        int gsrc = w % G4;
        int gate = gsrc >> 7, h = gsrc & 127;
        g_hh[a * G4 + 4 * h + gate] = s + bih[w] + bhh[w];
    }
}

// ==================== launch ====================
extern "C" void kernel_launch(void* const* d_in, const int* in_sizes, int n_in,
                              void* d_out, int out_size) {
    const float* obs = (const float*)d_in[0];
    const float* cv  = (const float*)d_in[1];
    const float* h0  = (const float*)d_in[2];
    const float* c0  = (const float*)d_in[3];
    const float* We  = (const float*)d_in[4];
    const float* be  = (const float*)d_in[5];
    const float* Wih = (const float*)d_in[6];
    const float* Whh = (const float*)d_in[7];
    const float* bih = (const float*)d_in[8];
    const float* bhh = (const float*)d_in[9];
    const float* Wg  = (const float*)d_in[10];
    const float* bg  = (const float*)d_in[11];
    const float* Wt  = (const float*)d_in[12];
    const float* bt  = (const float*)d_in[13];
    const int* alive = (n_in > 14) ? (const int*)d_in[14] : nullptr;
    float* dout = (float*)d_out;

    cudaFuncSetAttribute(k_lstm, cudaFuncAttributeMaxDynamicSharedMemorySize, SMEM_L);
    cudaFuncSetAttribute(k_out,  cudaFuncAttributeMaxDynamicSharedMemorySize, SMEM_G);

    k_hh<<<2048, 256>>>(h0, Whh, bih, bhh);
    k_prep_wih<<<1024, 256>>>(Wih);
    k_prep_w<<<dim3(8, 2), 256>>>(We, Wt);

    // 128-row tiles (round-14 config), pipelined B copies
    k_lstm<<<dim3(Bn / 128, An), 256, SMEM_L>>>(obs, cv, be, dout + BAH,
                                                dout + 2 * BAH, Wg, c0);

    k_amax<<<dim3(An, 4), 256>>>(bg);

    k_out<<<M_BIG / 128, 256, SMEM_G>>>(dout + BAH, dout, bt, alive);
}

// round 17
// speedup vs baseline: 1.1033x; 1.0066x over previous
#include <cuda_runtime.h>
#include <cuda_bf16.h>
#include <cuda_pipeline.h>
#include <math.h>
#include <stdint.h>

// Problem constants
constexpr int Bn = 4096;
constexpr int An = 32;
constexpr int Hn = 128;
constexpr int G4 = 4 * Hn;          // 512
constexpr int M_BIG = Bn * An;      // 131072
constexpr int BAH = Bn * An * Hn;   // 16,777,216

// -------------------- scratch --------------------
__device__ float g_hh[An * G4];                // interleaved (4h+gate) hidden bias
__device__ float g_logp[(size_t)An * Bn * 16]; // logit partials (8 MB)
__device__ unsigned long long g_argmax[An];
// pre-split weights (hi/lo bf16, chunk-linear 16B units)
__device__ __nv_bfloat16 g_wih_h[An * G4 * Hn];   // 4 MB, permuted gate layout
__device__ __nv_bfloat16 g_wih_l[An * G4 * Hn];
__device__ __nv_bfloat16 g_we_h[Hn * Hn], g_we_l[Hn * Hn];
__device__ __nv_bfloat16 g_wt_h[Hn * Hn], g_wt_l[Hn * Hn];

// ==================== helpers ====================
__device__ __forceinline__ uint32_t smem_u32(const void* p) {
    uint32_t a;
    asm("{ .reg .u64 t; cvta.to.shared.u64 t, %1; cvt.u32.u64 %0, t; }"
        : "=r"(a) : "l"(p));
    return a;
}
__device__ __forceinline__ uint32_t pk(float k0, float k1) {
    uint32_t r;
    asm("cvt.rn.satfinite.bf16x2.f32 %0, %1, %2;" : "=r"(r) : "f"(k1), "f"(k0));
    return r;
}
__device__ __forceinline__ void ldsm_x4(uint32_t* r, uint32_t addr) {
    asm volatile("ldmatrix.sync.aligned.m8n8.x4.shared.b16 {%0,%1,%2,%3}, [%4];"
                 : "=r"(r[0]), "=r"(r[1]), "=r"(r[2]), "=r"(r[3]) : "r"(addr));
}
__device__ __forceinline__ void mma_bf16(float* d, const uint32_t* a, const uint32_t* b) {
    asm volatile(
        "mma.sync.aligned.m16n8k16.row.col.f32.bf16.bf16.f32 "
        "{%0,%1,%2,%3}, {%4,%5,%6,%7}, {%8,%9}, {%0,%1,%2,%3};"
        : "+f"(d[0]), "+f"(d[1]), "+f"(d[2]), "+f"(d[3])
        : "r"(a[0]), "r"(a[1]), "r"(a[2]), "r"(a[3]), "r"(b[0]), "r"(b[1]));
}
// fast transcendentals (MUFU-based); error ~1e-6 << bf16-split noise ~1e-4
__device__ __forceinline__ float fsig(float x) {
    return __fdividef(1.0f, 1.0f + __expf(-x));
}
__device__ __forceinline__ float ftanh(float x) {
    float t = __expf(-2.0f * x);
    return __fdividef(1.0f - t, 1.0f + t);
}

// -------------------- SMEM layouts --------------------
constexpr int OF_AH = 0;
constexpr int OF_AL = 16384;
constexpr int OF_BH = 32768;
constexpr int OF_BL = 49152;           // tiles end 65536
constexpr int OF_MISC = 69632;         // stage (128x132 f32) aliases tiles
constexpr int SMEM_G = 72192;

constexpr int L_AH = 0;
constexpr int L_AL = 32768;
constexpr int L_BH = 65536;
constexpr int L_BL = 81920;            // tiles end 98304
constexpr int L_MISC = 98304;
constexpr int SMEM_L = 101888;         // 2 CTAs/SM

__device__ __forceinline__ uint32_t su(int row, int u) {
    return (uint32_t)(row * 128 + ((u ^ (row & 7)) << 4));
}
__device__ __forceinline__ uint32_t suA(int row, int u) {
    return (uint32_t)(row * 256 + (((u & 7) ^ (row & 7)) << 4) + ((u >> 3) << 7));
}
__device__ __forceinline__ int sidx(int r, int c) {
    return r * 64 + (c ^ ((r & 7) << 3));
}

// split 8 floats -> hi/lo bf16x2 quads at given swizzled byte offset
__device__ __forceinline__ void split8(char* sm, int hib, int lob, uint32_t off,
                                       const float* v) {
    float h[8];
    #pragma unroll
    for (int j = 0; j < 8; j++) h[j] = __bfloat162float(__float2bfloat16(v[j]));
    uint4 hi = make_uint4(pk(v[0], v[1]), pk(v[2], v[3]), pk(v[4], v[5]), pk(v[6], v[7]));
    uint4 lo = make_uint4(pk(v[0] - h[0], v[1] - h[1]), pk(v[2] - h[2], v[3] - h[3]),
                          pk(v[4] - h[4], v[5] - h[5]), pk(v[6] - h[6], v[7] - h[7]));
    *reinterpret_cast<uint4*>(sm + hib + off) = hi;
    *reinterpret_cast<uint4*>(sm + lob + off) = lo;
}

// split 8 floats into two global uint4 slots (for weight prep)
__device__ __forceinline__ void split8_g(__nv_bfloat16* gh, __nv_bfloat16* gl,
                                         const float* v) {
    float h[8];
    #pragma unroll
    for (int j = 0; j < 8; j++) h[j] = __bfloat162float(__float2bfloat16(v[j]));
    uint4 hi = make_uint4(pk(v[0], v[1]), pk(v[2], v[3]), pk(v[4], v[5]), pk(v[6], v[7]));
    uint4 lo = make_uint4(pk(v[0] - h[0], v[1] - h[1]), pk(v[2] - h[2], v[3] - h[3]),
                          pk(v[4] - h[4], v[5] - h[5]), pk(v[6] - h[6], v[7] - h[7]));
    *reinterpret_cast<uint4*>(gh) = hi;
    *reinterpret_cast<uint4*>(gl) = lo;
}

// copy a pre-split 128x64 chunk (1024 16B units x2) into swizzled tiles
__device__ __forceinline__ void copy_tile(char* sm, int hib, int lob,
                                          const __nv_bfloat16* __restrict__ wh,
                                          const __nv_bfloat16* __restrict__ wl,
                                          int tid) {
    #pragma unroll
    for (int i = 0; i < 4; i++) {
        int idx = tid + i * 256;
        int row = idx >> 3, u = idx & 7;
        uint32_t off = su(row, u);
        *reinterpret_cast<uint4*>(sm + hib + off) =
            *reinterpret_cast<const uint4*>(wh + idx * 8);
        *reinterpret_cast<uint4*>(sm + lob + off) =
            *reinterpret_cast<const uint4*>(wl + idx * 8);
    }
}

// cp.async copy of ONE k-half (u = s*4 .. s*4+3) of a 128x64 pre-split chunk
// into the L_BH/L_BL tiles.
__device__ __forceinline__ void copy_half_async(char* sm,
                                                const __nv_bfloat16* __restrict__ wh,
                                                const __nv_bfloat16* __restrict__ wl,
                                                int tid, int s) {
    #pragma unroll
    for (int i = 0; i < 2; i++) {
        int idx = tid + i * 256;          // 512: row(128) x uu(4)
        int row = idx >> 2, uu = idx & 3;
        int u = s * 4 + uu;
        uint32_t off = su(row, u);
        int gsrc = (row * 8 + u) * 8;
        __pipeline_memcpy_async(sm + L_BH + off, wh + gsrc, 16);
        __pipeline_memcpy_async(sm + L_BL + off, wl + gsrc, 16);
    }
}

// load+split a 128x64 fp32 chunk into hi/lo chunk tiles (su layout)
__device__ __forceinline__ void load_tile(char* sm, int hib, int lob,
                                          const float* __restrict__ src, int lda,
                                          int k0, int tid) {
    #pragma unroll
    for (int i = 0; i < 4; i++) {
        int idx = tid + i * 256;
        int row = idx >> 3, u = idx & 7;
        const float* p = src + (size_t)row * lda + k0 + u * 8;
        float v[8];
        float4 v0 = *reinterpret_cast<const float4*>(p);
        float4 v1 = *reinterpret_cast<const float4*>(p + 4);
        v[0] = v0.x; v[1] = v0.y; v[2] = v0.z; v[3] = v0.w;
        v[4] = v1.x; v[5] = v1.y; v[6] = v1.z; v[7] = v1.w;
        split8(sm, hib, lob, su(row, u), v);
    }
}

// load+split a 128x128 fp32 tile into hi/lo FULL-K (suA) tiles
__device__ __forceinline__ void load_tile_fullA(char* sm,
                                                const float* __restrict__ src,
                                                int lda, int tid) {
    #pragma unroll
    for (int i = 0; i < 8; i++) {
        int idx = tid + i * 256;          // 2048: row(128) x u(16)
        int row = idx >> 4, u = idx & 15;
        const float* p = src + (size_t)row * lda + u * 8;
        float v[8];
        float4 v0 = *reinterpret_cast<const float4*>(p);
        float4 v1 = *reinterpret_cast<const float4*>(p + 4);
        v[0] = v0.x; v[1] = v0.y; v[2] = v0.z; v[3] = v0.w;
        v[4] = v1.x; v[5] = v1.y; v[6] = v1.z; v[7] = v1.w;
        split8(sm, L_AH, L_AL, suA(row, u), v);
    }
}

// 3-pass split MMA over one 64-K chunk; chunk-layout A (k_out). Order hh/lh/hl.
__device__ __forceinline__ void mma_chunk(uint32_t sb, int aHi, int aLo, int bHi,
                                          int bLo, int wm, int wn, int lane,
                                          float acc[2][8][4]) {
    const int arow = (lane & 7) + ((lane >> 3) & 1) * 8;
    const int akq  = lane >> 4;
    const int bnt  = (lane >> 4) & 1;
    const int bkq  = (lane >> 3) & 1;
    const int brow = lane & 7;
    #pragma unroll
    for (int ks = 0; ks < 4; ks++) {
        uint32_t aH[2][4], aL[2][4], b[4][2];
        const int uA = ks * 2 + akq;
        const int uB = ks * 2 + bkq;
        #pragma unroll
        for (int mt = 0; mt < 2; mt++) {
            int r = wm + mt * 16 + arow;
            uint32_t offA = su(r, uA);
            ldsm_x4(aH[mt], sb + aHi + offA);
            ldsm_x4(aL[mt], sb + aLo + offA);
        }
        #pragma unroll
        for (int hf = 0; hf < 2; hf++) {
            #pragma unroll
            for (int nt2 = 0; nt2 < 4; nt2 += 2)
                ldsm_x4(&b[nt2][0],
                        sb + bHi + su(wn + (hf * 4 + nt2 + bnt) * 8 + brow, uB));
            #pragma unroll
            for (int mt = 0; mt < 2; mt++)
                #pragma unroll
                for (int nt = 0; nt < 4; nt++)
                    mma_bf16(acc[mt][hf * 4 + nt], aH[mt], b[nt]);
            #pragma unroll
            for (int mt = 0; mt < 2; mt++)
                #pragma unroll
                for (int nt = 0; nt < 4; nt++)
                    mma_bf16(acc[mt][hf * 4 + nt], aL[mt], b[nt]);
            #pragma unroll
            for (int nt2 = 0; nt2 < 4; nt2 += 2)
                ldsm_x4(&b[nt2][0],
                        sb + bLo + su(wn + (hf * 4 + nt2 + bnt) * 8 + brow, uB));
            #pragma unroll
            for (int mt = 0; mt < 2; mt++)
                #pragma unroll
                for (int nt = 0; nt < 4; nt++)
                    mma_bf16(acc[mt][hf * 4 + nt], aH[mt], b[nt]);
        }
    }
}

// two-ks MMA on k-half s of chunk kcA; A from full-K (suA) L_AH/L_AL tiles.
// Identical per-accumulator contribution order (ks ascending, hh/lh/hl).
__device__ __forceinline__ void mma_half(uint32_t sb, int kcA, int s, int wm, int wn,
                                         int lane, float acc[2][8][4]) {
    const int arow = (lane & 7) + ((lane >> 3) & 1) * 8;
    const int akq  = lane >> 4;
    const int bnt  = (lane >> 4) & 1;
    const int bkq  = (lane >> 3) & 1;
    const int brow = lane & 7;
    #pragma unroll
    for (int j = 0; j < 2; j++) {
        int ks = s * 2 + j;
        uint32_t aH[2][4], aL[2][4], b[4][2];
        const int uA = kcA * 8 + ks * 2 + akq;
        const int uB = ks * 2 + bkq;
        #pragma unroll
        for (int mt = 0; mt < 2; mt++) {
            int r = wm + mt * 16 + arow;
            uint32_t offA = suA(r, uA);
            ldsm_x4(aH[mt], sb + L_AH + offA);
            ldsm_x4(aL[mt], sb + L_AL + offA);
        }
        #pragma unroll
        for (int hf = 0; hf < 2; hf++) {
            #pragma unroll
            for (int nt2 = 0; nt2 < 4; nt2 += 2)
                ldsm_x4(&b[nt2][0],
                        sb + L_BH + su(wn + (hf * 4 + nt2 + bnt) * 8 + brow, uB));
            #pragma unroll
            for (int mt = 0; mt < 2; mt++)
                #pragma unroll
                for (int nt = 0; nt < 4; nt++)
                    mma_bf16(acc[mt][hf * 4 + nt], aH[mt], b[nt]);
            #pragma unroll
            for (int mt = 0; mt < 2; mt++)
                #pragma unroll
                for (int nt = 0; nt < 4; nt++)
                    mma_bf16(acc[mt][hf * 4 + nt], aL[mt], b[nt]);
            #pragma unroll
            for (int nt2 = 0; nt2 < 4; nt2 += 2)
                ldsm_x4(&b[nt2][0],
                        sb + L_BL + su(wn + (hf * 4 + nt2 + bnt) * 8 + brow, uB));
            #pragma unroll
            for (int mt = 0; mt < 2; mt++)
                #pragma unroll
                for (int nt = 0; nt < 4; nt++)
                    mma_bf16(acc[mt][hf * 4 + nt], aH[mt], b[nt]);
        }
    }
}

// pipelined 128x128-K GEMM phase over 4 (kc,s) halves; weights chunk-linear.
__device__ __forceinline__ void gemm_pipelined(char* sm, uint32_t sb,
                                               const __nv_bfloat16* __restrict__ wh,
                                               const __nv_bfloat16* __restrict__ wl,
                                               size_t chunk_stride,
                                               int tid, int wm, int wn, int lane,
                                               float acc[2][8][4]) {
    copy_half_async(sm, wh, wl, tid, 0);
    __pipeline_commit();
    #pragma unroll 1
    for (int t = 0; t < 4; t++) {
        int kc = t >> 1, s = t & 1;
        __pipeline_wait_prior(0);
        __syncthreads();           // half t in smem everywhere; mma(t-1) done
        if (t < 3) {
            int t2 = t + 1;
            copy_half_async(sm, wh + (size_t)(t2 >> 1) * chunk_stride,
                            wl + (size_t)(t2 >> 1) * chunk_stride, tid, t2 & 1);
            __pipeline_commit();
        }
        mma_half(sb, kc, s, wm, wn, lane, acc);
    }
}

__device__ __forceinline__ void stage_acc(float* stage, int wm, int wn, int lane,
                                          float acc[2][8][4]) {
    const int grp = lane >> 2, qp = lane & 3;
    #pragma unroll
    for (int mt = 0; mt < 2; mt++)
        #pragma unroll
        for (int nt = 0; nt < 8; nt++) {
            int r = wm + mt * 16 + grp;
            int c = wn + nt * 8 + qp * 2;
            stage[r * 132 + c] = acc[mt][nt][0];
            stage[r * 132 + c + 1] = acc[mt][nt][1];
            stage[(r + 8) * 132 + c] = acc[mt][nt][2];
            stage[(r + 8) * 132 + c + 1] = acc[mt][nt][3];
        }
}

__device__ __forceinline__ void stage_half(float* stage, int wm, int wn, int ph,
                                           int lane, float acc[2][8][4]) {
    if (wn == ph * 64) {
        const int grp = lane >> 2, qp = lane & 3;
        #pragma unroll
        for (int mt = 0; mt < 2; mt++)
            #pragma unroll
            for (int nt = 0; nt < 8; nt++) {
                int r = wm + mt * 16 + grp;
                int c = nt * 8 + qp * 2;
                *reinterpret_cast<float2*>(&stage[sidx(r, c)]) =
                    make_float2(acc[mt][nt][0], acc[mt][nt][1]);
                *reinterpret_cast<float2*>(&stage[sidx(r + 8, c)]) =
                    make_float2(acc[mt][nt][2], acc[mt][nt][3]);
            }
    }
}

#define ZERO_ACC(acc)                                                     \
    _Pragma("unroll") for (int mt = 0; mt < 2; mt++)                      \
        _Pragma("unroll") for (int nt = 0; nt < 8; nt++)                  \
            _Pragma("unroll") for (int e = 0; e < 4; e++) acc[mt][nt][e] = 0.f;

// ==================== prep: split weights ====================
__global__ void k_prep_wih(const float* __restrict__ Wih) {
    int g = blockIdx.x * blockDim.x + threadIdx.x;    // 262144 units
    int z = g >> 13, r = g & 8191;
    int nc = r >> 11, r2 = r & 2047;
    int kc = r2 >> 10, t = r2 & 1023;
    int row = t >> 3, u = t & 7;
    int ng = nc * 128 + row;
    int srow = (ng & 3) * 128 + (ng >> 2);
    const float* p = Wih + ((size_t)z * G4 + srow) * Hn + kc * 64 + u * 8;
    float v[8];
    float4 v0 = *reinterpret_cast<const float4*>(p);
    float4 v1 = *reinterpret_cast<const float4*>(p + 4);
    v[0] = v0.x; v[1] = v0.y; v[2] = v0.z; v[3] = v0.w;
    v[4] = v1.x; v[5] = v1.y; v[6] = v1.z; v[7] = v1.w;
    split8_g(&g_wih_h[(size_t)g * 8], &g_wih_l[(size_t)g * 8], v);
}

__global__ void k_prep_w(const float* __restrict__ We, const float* __restrict__ Wt) {
    int g = blockIdx.x * blockDim.x + threadIdx.x;    // 2048 units (grid 8 x 2)
    const float* W = blockIdx.y ? Wt : We;
    __nv_bfloat16* gh = blockIdx.y ? g_wt_h : g_we_h;
    __nv_bfloat16* gl = blockIdx.y ? g_wt_l : g_we_l;
    int kc = g >> 10, t = g & 1023;
    int row = t >> 3, u = t & 7;
    const float* p = W + (size_t)row * Hn + kc * 64 + u * 8;
    float v[8];
    float4 v0 = *reinterpret_cast<const float4*>(p);
    float4 v1 = *reinterpret_cast<const float4*>(p + 4);
    v[0] = v0.x; v[1] = v0.y; v[2] = v0.z; v[3] = v0.w;
    v[4] = v1.x; v[5] = v1.y; v[6] = v1.z; v[7] = v1.w;
    split8_g(&gh[(size_t)g * 8], &gl[(size_t)g * 8], v);
}

// ==================== k_lstm: fully pipelined enc+gates+LSTM ====================
// grid(Bn/128, An), 2 CTAs/SM
__global__ __launch_bounds__(256, 2)
void k_lstm(const float* __restrict__ obs, const float* __restrict__ cv,
            const float* __restrict__ be, float* __restrict__ h1,
            float* __restrict__ c1, const float* __restrict__ Wg,
            const float* __restrict__ c0) {
    extern __shared__ char sm[];
    float* stage = (float*)(sm + L_BH);        // 32 KB stage aliases B tiles
    float* mi = (float*)(sm + L_MISC);
    float* s_bias = mi;            // 512
    float* s_c0   = mi + 512;      // 128
    float* s_wg   = mi + 640;      // 256

    const int tid = threadIdx.x, wid = tid >> 5, lane = tid & 31;
    const int m0 = blockIdx.x * 128;
    const int z  = blockIdx.y;
    const uint32_t sb = smem_u32(sm);
    const int wm = (wid & 3) * 32, wn = (wid >> 2) * 64;

    for (int i = tid; i < 512; i += 256) s_bias[i] = g_hh[z * G4 + i];
    if (tid < 128) s_c0[tid] = c0[z * Hn + tid];
    if (tid < 256) s_wg[tid] = Wg[z * 256 + tid];

    // ---------- phase 1: enc tile = obs_slice @ We^T (pipelined) ----------
    load_tile_fullA(sm, obs + ((size_t)m0 * An + z) * Hn, An * Hn, tid);
    float acc[2][8][4];
    ZERO_ACC(acc);
    gemm_pipelined(sm, sb, g_we_h, g_we_l, 8192, tid, wm, wn, lane, acc);

    // ---------- phase 2: + be + cv, split into resident full-K A tiles ----------
    #pragma unroll 1
    for (int ph = 0; ph < 2; ph++) {
        __syncthreads();
        stage_half(stage, wm, wn, ph, lane, acc);
        __syncthreads();
        #pragma unroll
        for (int i = 0; i < 4; i++) {
            int idx = tid + i * 256;
            int row = idx >> 3, u = idx & 7;
            int cb = ph * 64 + u * 8;
            const float* sp = &stage[sidx(row, u * 8)];
            const float* cp = cv + ((size_t)(m0 + row) * An + z) * Hn + cb;
            float v[8];
            #pragma unroll
            for (int j = 0; j < 8; j += 4) {
                float4 sv = *reinterpret_cast<const float4*>(sp + j);
                float4 bv = *reinterpret_cast<const float4*>(be + cb + j);
                float4 cvv = *reinterpret_cast<const float4*>(cp + j);
                v[j + 0] = sv.x + bv.x + cvv.x;
                v[j + 1] = sv.y + bv.y + cvv.y;
                v[j + 2] = sv.z + bv.z + cvv.z;
                v[j + 3] = sv.w + bv.w + cvv.w;
            }
            split8(sm, L_AH, L_AL, suA(row, ph * 8 + u), v);
        }
    }

    // ---------- phase 3: gates GEMM (pipelined B) + LSTM epilogue ----------
    #pragma unroll 1
    for (int nc = 0; nc < 4; nc++) {
        ZERO_ACC(acc);
        __syncthreads();   // prior stage/epilogue (or phase-2) reads of B region done
        {
            size_t base = ((size_t)(z * 4 + nc) * 2) << 13;
            gemm_pipelined(sm, sb, g_wih_h + base, g_wih_l + base, 8192,
                           tid, wm, wn, lane, acc);
        }
        // epilogue in two 64-col halves (stage aliases B region; pipe drained)
        #pragma unroll 1
        for (int ph = 0; ph < 2; ph++) {
            __syncthreads();
            stage_half(stage, wm, wn, ph, lane, acc);
            __syncthreads();
            #pragma unroll
            for (int i = 0; i < 8; i++) {
                int idx = tid + i * 256;       // 2048: 128 rows x 16 hl
                int r = idx >> 4, hl = idx & 15;
                float4 g = *reinterpret_cast<float4*>(&stage[sidx(r, 4 * hl)]);
                int gb = nc * 128 + ph * 64 + 4 * hl;
                int h = nc * 32 + ph * 16 + hl;
                float ig = g.x + s_bias[gb + 0];
                float fg = g.y + s_bias[gb + 1];
                float gg = g.z + s_bias[gb + 2];
                float og = g.w + s_bias[gb + 3];
                float cc = fsig(fg) * s_c0[h] + fsig(ig) * ftanh(gg);
                float hv = fsig(og) * ftanh(cc);
                size_t off = ((size_t)(m0 + r) * An + z) * 128 + h;
                h1[off] = hv;
                c1[off] = cc;
                float p0 = hv * s_wg[h];
                float p1 = hv * s_wg[128 + h];
                #pragma unroll
                for (int o = 8; o; o >>= 1) {
                    p0 += __shfl_xor_sync(0xFFFFFFFFu, p0, o);
                    p1 += __shfl_xor_sync(0xFFFFFFFFu, p1, o);
                }
                if ((lane & 15) == 0)
                    *reinterpret_cast<float2*>(
                        &g_logp[(((size_t)z * Bn) + (m0 + r)) * 16 + nc * 4 + ph * 2]) =
                        make_float2(p0, p1);
            }
        }
    }
}

// ==================== k_amax ====================
__global__ __launch_bounds__(256)
void k_amax(const float* __restrict__ bg) {
    __shared__ unsigned long long sred[8];
    const int a = blockIdx.x, j = blockIdx.y;
    const int tid = threadIdx.x, wid = tid >> 5, lane = tid & 31;
    float b0 = bg[a * 2 + 0], b1 = bg[a * 2 + 1];
    unsigned long long best = 0ull;
    #pragma unroll
    for (int i = 0; i < 4; i++) {
        int b = j * 1024 + i * 256 + tid;
        const float4* lp = reinterpret_cast<const float4*>(
            &g_logp[((size_t)a * Bn + b) * 16]);
        float4 q0 = lp[0], q1 = lp[1], q2 = lp[2], q3 = lp[3];
        float l0 = ((q0.x + q0.z) + (q1.x + q1.z)) + ((q2.x + q2.z) + (q3.x + q3.z)) + b0;
        float l1 = ((q0.y + q0.w) + (q1.y + q1.w)) + ((q2.y + q2.w) + (q3.y + q3.w)) + b1;
        float d = l0 - l1;
        float p = 1.0f / (1.0f + expf(-fabsf(d)));
        unsigned pidx = 2u * (unsigned)b + (d >= 0.f ? 0u : 1u);
        unsigned long long packed =
            ((unsigned long long)__float_as_uint(p) << 32) | (0xFFFFFFFFu - pidx);
        if (packed > best) best = packed;
    }
    #pragma unroll
    for (int o = 16; o; o >>= 1) {
        unsigned long long other = __shfl_xor_sync(0xFFFFFFFFu, best, o);
        if (other > best) best = other;
    }
    if (lane == 0) sred[wid] = best;
    __syncthreads();
    if (tid == 0) {
        unsigned long long m = sred[0];
        #pragma unroll
        for (int i = 1; i < 8; i++) if (sred[i] > m) m = sred[i];
        atomicMax(&g_argmax[a], m);
    }
}

// ==================== k_out ====================
__global__ __launch_bounds__(256, 2)
void k_out(const float* __restrict__ h1, float* __restrict__ out,
           const float* __restrict__ bt, const int* __restrict__ alive) {
    extern __shared__ char sm[];
    float* stage = (float*)sm;
    float* mi = (float*)(sm + OF_MISC);
    float* sidxv = mi;             // 32
    float* scs   = mi + 32;        // 512

    const int tid = threadIdx.x, wid = tid >> 5, lane = tid & 31;
    const int m0 = blockIdx.x * 128;
    const uint32_t sb = smem_u32(sm);
    const int wm = (wid & 3) * 32, wn = (wid >> 2) * 64;

    // prefetch Wt chunk kc=0 via cp.async (overlaps comm_sum below)
    #pragma unroll
    for (int i = 0; i < 4; i++) {
        int idx = tid + i * 256;
        int row = idx >> 3, u = idx & 7;
        uint32_t off = su(row, u);
        __pipeline_memcpy_async(sm + OF_BH + off, g_wt_h + idx * 8, 16);
        __pipeline_memcpy_async(sm + OF_BL + off, g_wt_l + idx * 8, 16);
    }
    __pipeline_commit();

    if (tid < 32)
        sidxv[tid] = (float)(0xFFFFFFFFu - (unsigned)(g_argmax[tid] & 0xFFFFFFFFull));
    __syncthreads();

    {
        int v = alive ? *alive : An;
        if (v < 0 || v > (1 << 20)) v = (int)__int_as_float(v);
        float norm = v ? 1.0f / (float)(v - 1) : 1.0f;
        #pragma unroll 1
        for (int t = tid; t < 512; t += 256) {
            int bl = t >> 7, h = t & 127;
            const float* hp = h1 + (size_t)(m0 + bl * 32) * 128 + h;
            float s = 0.f;
            #pragma unroll
            for (int a = 0; a < An; a++) s += sidxv[a] * hp[a * 128];
            scs[bl * 128 + h] = norm * s;
        }
    }
    __syncthreads();

    float acc[2][8][4];
    ZERO_ACC(acc);
    #pragma unroll 1
    for (int kc = 0; kc < 2; kc++) {
        #pragma unroll
        for (int i = 0; i < 4; i++) {
            int idx = tid + i * 256;
            int row = idx >> 3, u = idx & 7;
            int bl = row >> 5, a = row & 31;
            float ia = sidxv[a];
            const float* p = h1 + (size_t)(m0 + row) * 128 + kc * 64 + u * 8;
            float v[8];
            float4 v0 = *reinterpret_cast<const float4*>(p);
            float4 v1 = *reinterpret_cast<const float4*>(p + 4);
            const float* sc = &scs[bl * 128 + kc * 64 + u * 8];
            v[0] = sc[0] - ia * v0.x; v[1] = sc[1] - ia * v0.y;
            v[2] = sc[2] - ia * v0.z; v[3] = sc[3] - ia * v0.w;
            v[4] = sc[4] - ia * v1.x; v[5] = sc[5] - ia * v1.y;
            v[6] = sc[6] - ia * v1.z; v[7] = sc[7] - ia * v1.w;
            split8(sm, OF_AH, OF_AL, su(row, u), v);
        }
        if (kc == 0) {
            __pipeline_wait_prior(0);
        } else {
            copy_tile(sm, OF_BH, OF_BL, g_wt_h + 8192, g_wt_l + 8192, tid);
        }
        __syncthreads();
        mma_chunk(sb, OF_AH, OF_AL, OF_BH, OF_BL, wm, wn, lane, acc);
        __syncthreads();
    }
    stage_acc(stage, wm, wn, lane, acc);
    __syncthreads();

    #pragma unroll 1
    for (int rr = 0; rr < 16; rr++) {
        int r = wid * 16 + rr;
        float v[4];
        #pragma unroll
        for (int j = 0; j < 4; j++)
            v[j] = stage[r * 132 + lane * 4 + j] + bt[lane * 4 + j];
        float mx = fmaxf(fmaxf(v[0], v[1]), fmaxf(v[2], v[3]));
        #pragma unroll
        for (int o = 16; o; o >>= 1)
            mx = fmaxf(mx, __shfl_xor_sync(0xFFFFFFFFu, mx, o));
        float s = 0.f;
        #pragma unroll
        for (int j = 0; j < 4; j++) { v[j] = __expf(v[j] - mx); s += v[j]; }
        #pragma unroll
        for (int o = 16; o; o >>= 1)
            s += __shfl_xor_sync(0xFFFFFFFFu, s, o);
        float inv = __fdividef(1.0f, s);
        float4 o4 = make_float4(v[0] * inv, v[1] * inv, v[2] * inv, v[3] * inv);
        *reinterpret_cast<float4*>(out + (size_t)(m0 + r) * 128 + lane * 4) = o4;
    }
}

// ==================== k_hh (prep) ====================
__global__ void k_hh(const float* __restrict__ h0, const float* __restrict__ Whh,
                     const float* __restrict__ bih, const float* __restrict__ bhh) {
    if (blockIdx.x == 0 && threadIdx.x < An) g_argmax[threadIdx.x] = 0ull;
    int w = (blockIdx.x * blockDim.x + threadIdx.x) >> 5;
    int lane = threadIdx.x & 31;
    if (w >= An * G4) return;
    int a = w / G4;
    float4 hv = *reinterpret_cast<const float4*>(h0 + a * Hn + lane * 4);
    float4 wv = *reinterpret_cast<const float4*>(Whh + (size_t)w * Hn + lane * 4);
    float s = hv.x * wv.x + hv.y * wv.y + hv.z * wv.z + hv.w * wv.w;
    #pragma unroll
    for (int off = 16; off; off >>= 1) s += __shfl_xor_sync(0xFFFFFFFFu, s, off);
    if (lane == 0) {
        int gsrc = w % G4;
        int gate = gsrc >> 7, h = gsrc & 127;
        g_hh[a * G4 + 4 * h + gate] = s + bih[w] + bhh[w];
    }
}

// ==================== launch ====================
extern "C" void kernel_launch(void* const* d_in, const int* in_sizes, int n_in,
                              void* d_out, int out_size) {
    const float* obs = (const float*)d_in[0];
    const float* cv  = (const float*)d_in[1];
    const float* h0  = (const float*)d_in[2];
    const float* c0  = (const float*)d_in[3];
    const float* We  = (const float*)d_in[4];
    const float* be  = (const float*)d_in[5];
    const float* Wih = (const float*)d_in[6];
    const float* Whh = (const float*)d_in[7];
    const float* bih = (const float*)d_in[8];
    const float* bhh = (const float*)d_in[9];
    const float* Wg  = (const float*)d_in[10];
    const float* bg  = (const float*)d_in[11];
    const float* Wt  = (const float*)d_in[12];
    const float* bt  = (const float*)d_in[13];
    const int* alive = (n_in > 14) ? (const int*)d_in[14] : nullptr;
    float* dout = (float*)d_out;

    cudaFuncSetAttribute(k_lstm, cudaFuncAttributeMaxDynamicSharedMemorySize, SMEM_L);
    cudaFuncSetAttribute(k_out,  cudaFuncAttributeMaxDynamicSharedMemorySize, SMEM_G);

    k_hh<<<2048, 256>>>(h0, Whh, bih, bhh);
    k_prep_wih<<<1024, 256>>>(Wih);
    k_prep_w<<<dim3(8, 2), 256>>>(We, Wt);

    k_lstm<<<dim3(Bn / 128, An), 256, SMEM_L>>>(obs, cv, be, dout + BAH,
                                                dout + 2 * BAH, Wg, c0);

    k_amax<<<dim3(An, 4), 256>>>(bg);

    k_out<<<M_BIG / 128, 256, SMEM_G>>>(dout + BAH, dout, bt, alive);
}